// round 11
// baseline (speedup 1.0000x reference)
#include <cuda_runtime.h>
#include <cstdint>

// Problem constants (fixed by the reference)
#define Bn       8
#define Nn       32768
#define CINn     128
#define Mn       (Nn / 4)          // 8192 sampled points
#define CLUSTER  8                 // CTAs per batch (one cluster)
#define PTS_CTA  (Nn / CLUSTER)    // 4096 points per CTA
#define THREADS  512
#define PTS_THR  (PTS_CTA / THREADS) // 8 points per thread
#define PAIRS    (PTS_THR / 2)       // 4 f32x2 pairs per thread
#define NWARPS   (THREADS / 32)

// Scratch: selected indices per batch (allowed: __device__ global, no alloc)
__device__ int g_idx[Bn * Mn];

__device__ __forceinline__ uint32_t smem_u32(const void* p) {
    return (uint32_t)__cvta_generic_to_shared(p);
}

// ---- f32x2 packed fp32 helpers (each half = independent rn op, bit-exact) ----
__device__ __forceinline__ void f2_add(unsigned long long& d,
                                       unsigned long long a, unsigned long long b) {
    asm("add.rn.f32x2 %0, %1, %2;" : "=l"(d) : "l"(a), "l"(b));
}
__device__ __forceinline__ void f2_mul(unsigned long long& d,
                                       unsigned long long a, unsigned long long b) {
    asm("mul.rn.f32x2 %0, %1, %2;" : "=l"(d) : "l"(a), "l"(b));
}
__device__ __forceinline__ void f2_fma(unsigned long long& d, unsigned long long a,
                                       unsigned long long b, unsigned long long c) {
    asm("fma.rn.f32x2 %0, %1, %2, %3;" : "=l"(d) : "l"(a), "l"(b), "l"(c));
}
__device__ __forceinline__ unsigned long long f2_pack(float lo, float hi) {
    unsigned long long r;
    asm("mov.b64 %0, {%1, %2};" : "=l"(r) : "f"(lo), "f"(hi));
    return r;
}
__device__ __forceinline__ void f2_unpack(unsigned long long v, float& lo, float& hi) {
    asm("mov.b64 {%0, %1}, %2;" : "=f"(lo), "=f"(hi) : "l"(v));
}

// ---------------------------------------------------------------------------
// FPS kernel: one cluster of 8 CTAs per batch. xyz slice + running distance
// live entirely in registers (as f32x2 pairs). Per-iteration cross-CTA argmax:
// redux.sync warp reduce -> smem -> warp0 block reduce -> 8 parallel lanes
// push {packed, xyz} to all CTAs via DSMEM + mbarrier.arrive.release.cluster.
// Receivers try_wait (acquire.cluster), pick max of 8 slots.
// Tie-break: LOWEST index everywhere (frozen by bisection). Distance:
// fma(dz,dz, fma(dx,dx, dy*dy)) (frozen). dx computed as px + (-cx) (exact).
// ---------------------------------------------------------------------------
__global__ void __cluster_dims__(CLUSTER, 1, 1) __launch_bounds__(THREADS, 1)
fps_kernel(const float* __restrict__ xyz)
{
    // slot = { pk = dist_bits<<32 | ~idx,  xy packed,  z (low 4B) }
    __shared__ unsigned long long slots[2][CLUSTER][3];
    __shared__ unsigned long long mbar[2];
    __shared__ unsigned           s_bits[NWARPS];
    __shared__ unsigned           s_idx[NWARPS];
    __shared__ unsigned long long s_xy[NWARPS];
    __shared__ float              s_z[NWARPS];

    const int tid  = threadIdx.x;
    const int lane = tid & 31;
    const int warp = tid >> 5;
    const int b    = blockIdx.x / CLUSTER;   // batch
    const int rank = blockIdx.x % CLUSTER;   // cta rank within cluster

    const float* __restrict__ xb = xyz + (size_t)b * 3 * Nn;
    const float* __restrict__ yb = xb + Nn;
    const float* __restrict__ zb = xb + 2 * Nn;
    const int base = rank * PTS_CTA;

    // mbarrier init (count = 8 arrivals: one pusher lane per CTA)
    if (tid == 0) {
        asm volatile("mbarrier.init.shared.b64 [%0], %1;"
                     :: "r"(smem_u32(&mbar[0])), "r"(CLUSTER) : "memory");
        asm volatile("mbarrier.init.shared.b64 [%0], %1;"
                     :: "r"(smem_u32(&mbar[1])), "r"(CLUSTER) : "memory");
    }
    asm volatile("barrier.cluster.arrive.aligned;" ::: "memory");

    // Register-resident point slice (f32x2 pairs) + running min-distance
    unsigned long long pxu[PAIRS], pyu[PAIRS], pzu[PAIRS];
    float dist[PTS_THR];
#pragma unroll
    for (int k = 0; k < PAIRS; k++) {
        int g0 = base + (2 * k) * THREADS + tid;       // coalesced loads
        int g1 = g0 + THREADS;
        pxu[k] = f2_pack(xb[g0], xb[g1]);
        pyu[k] = f2_pack(yb[g0], yb[g1]);
        pzu[k] = f2_pack(zb[g0], zb[g1]);
        dist[2 * k] = 1e10f;
        dist[2 * k + 1] = 1e10f;
    }

    // Initial farthest = point 0; centroid negated + packed
    float c0x = xb[0], c0y = yb[0], c0z = zb[0];
    unsigned long long ncx2 = f2_pack(-c0x, -c0x);
    unsigned long long ncy2 = f2_pack(-c0y, -c0y);
    unsigned long long ncz2 = f2_pack(-c0z, -c0z);
    int far = 0;

    // All CTAs' mbarriers initialized before first remote arrive
    asm volatile("barrier.cluster.wait.aligned;" ::: "memory");

    for (int i = 0; i < Mn; i++) {
        if (rank == 0 && tid == 0) g_idx[b * Mn + i] = far;
        const int parity = i & 1;
        const unsigned phase = (unsigned)((i >> 1) & 1);

        // ---- update distances (f32x2) + thread-local argmax (bd, bi) ----
        float bd = -1.0f;
        unsigned bi = 0;
#pragma unroll
        for (int k = 0; k < PAIRS; k++) {
            unsigned long long dx2, dy2, dz2, t;
            f2_add(dx2, pxu[k], ncx2);          // px - cx  (exact: a + (-b))
            f2_add(dy2, pyu[k], ncy2);
            f2_add(dz2, pzu[k], ncz2);
            f2_mul(t, dy2, dy2);                // dy*dy
            f2_fma(t, dx2, dx2, t);             // fma(dx,dx, dy*dy)
            f2_fma(t, dz2, dz2, t);             // fma(dz,dz, ...)   (frozen order)
            float d0, d1;
            f2_unpack(t, d0, d1);
            float nd0 = fminf(dist[2 * k], d0);     dist[2 * k] = nd0;
            float nd1 = fminf(dist[2 * k + 1], d1); dist[2 * k + 1] = nd1;
            unsigned g0 = (unsigned)(base + (2 * k) * THREADS + tid);
            if (nd0 > bd) { bd = nd0; bi = g0; }            // strict > : lowest idx
            if (nd1 > bd) { bd = nd1; bi = g0 + THREADS; }
        }

        // ---- warp argmax via redux.sync (max bits, then min idx among max) ----
        unsigned bits = __float_as_uint(bd);
        unsigned mx = __reduce_max_sync(0xffffffffu, bits);
        unsigned cand = (bits == mx) ? bi : 0xffffffffu;
        unsigned mn = __reduce_min_sync(0xffffffffu, cand);

        if (bits == mx && bi == mn) {           // exactly one lane (idx unique)
            float wx = 0.f, wy = 0.f, wz = 0.f;
#pragma unroll
            for (int k = 0; k < PAIRS; k++) {
                float ax, ah, ay, yh, az, zh;
                f2_unpack(pxu[k], ax, ah);
                f2_unpack(pyu[k], ay, yh);
                f2_unpack(pzu[k], az, zh);
                unsigned g0 = (unsigned)(base + (2 * k) * THREADS + tid);
                if (g0 == mn)           { wx = ax; wy = ay; wz = az; }
                if (g0 + THREADS == mn) { wx = ah; wy = yh; wz = zh; }
            }
            s_bits[warp] = mx;
            s_idx[warp]  = mn;
            s_xy[warp]   = f2_pack(wx, wy);
            s_z[warp]    = wz;
        }
        __syncthreads();

        // ---- warp0: block argmax over 16 warp winners, then 8-lane push ----
        if (warp == 0) {
            unsigned bits2 = (lane < NWARPS) ? s_bits[lane] : 0u;
            unsigned idx2  = (lane < NWARPS) ? s_idx[lane]  : 0xffffffffu;
            unsigned long long xy2 = (lane < NWARPS) ? s_xy[lane] : 0ull;
            float z2 = (lane < NWARPS) ? s_z[lane] : 0.f;

            unsigned mx2 = __reduce_max_sync(0xffffffffu, bits2);
            unsigned cand2 = (lane < NWARPS && bits2 == mx2) ? idx2 : 0xffffffffu;
            unsigned mn2 = __reduce_min_sync(0xffffffffu, cand2);

            bool win = (lane < NWARPS) && (bits2 == mx2) && (idx2 == mn2);
            unsigned bal = __ballot_sync(0xffffffffu, win);
            int wl = __ffs(bal) - 1;
            unsigned long long xyw = __shfl_sync(0xffffffffu, xy2, wl);
            float zw = __shfl_sync(0xffffffffu, z2, wl);

            if (lane < CLUSTER) {
                unsigned long long pk =
                    ((unsigned long long)mx2 << 32) | (unsigned)(~mn2);
                uint32_t laddr = smem_u32(&slots[parity][rank][0]);
                uint32_t lmbar = smem_u32(&mbar[parity]);
                uint32_t ra, rm;
                asm("mapa.shared::cluster.u32 %0, %1, %2;"
                    : "=r"(ra) : "r"(laddr), "r"(lane));
                asm("mapa.shared::cluster.u32 %0, %1, %2;"
                    : "=r"(rm) : "r"(lmbar), "r"(lane));
                asm volatile("st.shared::cluster.b64 [%0], %1;"
                             :: "r"(ra), "l"(pk) : "memory");
                asm volatile("st.shared::cluster.b64 [%0+8], %1;"
                             :: "r"(ra), "l"(xyw) : "memory");
                asm volatile("st.shared::cluster.b32 [%0+16], %1;"
                             :: "r"(ra), "r"(__float_as_uint(zw)) : "memory");
                asm volatile(
                    "mbarrier.arrive.release.cluster.shared::cluster.b64 _, [%0];"
                    :: "r"(rm) : "memory");
            }
        }

        // ---- all threads: wait for 8 arrivals, pick cluster winner ----
        {
            uint32_t maddr = smem_u32(&mbar[parity]);
            asm volatile(
                "{\n\t.reg .pred P;\n"
                "WAITLP_%=:\n\t"
                "mbarrier.try_wait.parity.acquire.cluster.shared::cta.b64 P, [%0], %1, 0x989680;\n\t"
                "@!P bra WAITLP_%=;\n\t}"
                :: "r"(maddr), "r"(phase) : "memory");
        }
        unsigned long long w = slots[parity][0][0];
        int wc = 0;
#pragma unroll
        for (int c = 1; c < CLUSTER; c++) {
            unsigned long long v = slots[parity][c][0];
            if (v > w) { w = v; wc = c; }   // pk unique (idx embedded)
        }
        far = (int)(~(unsigned)w);
        unsigned long long xyw = slots[parity][wc][1];
        float ncx, ncy;
        f2_unpack(xyw, ncx, ncy);
        float ncz = __uint_as_float((unsigned)slots[parity][wc][2]);
        ncx2 = f2_pack(-ncx, -ncx);
        ncy2 = f2_pack(-ncy, -ncy);
        ncz2 = f2_pack(-ncz, -ncz);
    }
}

// ---------------------------------------------------------------------------
// Gather epilogue: out = concat( sampled_xyz [B,3,M], sampled_feature [B,Cin,M] )
// ---------------------------------------------------------------------------
__global__ void gather_kernel(const float* __restrict__ xyz,
                              const float* __restrict__ feat,
                              float* __restrict__ out)
{
    const int P1  = Bn * 3 * Mn;
    const int TOT = P1 + Bn * CINn * Mn;
    int t = blockIdx.x * blockDim.x + threadIdx.x;
    if (t >= TOT) return;
    if (t < P1) {
        int b = t / (3 * Mn);
        int rem = t - b * 3 * Mn;
        int c = rem / Mn;
        int m = rem - c * Mn;
        int idx = g_idx[b * Mn + m];
        out[t] = xyz[(size_t)b * 3 * Nn + (size_t)c * Nn + idx];
    } else {
        int u = t - P1;
        int b = u / (CINn * Mn);
        int rem = u - b * CINn * Mn;
        int c = rem / Mn;
        int m = rem - c * Mn;
        int idx = g_idx[b * Mn + m];
        out[t] = feat[(size_t)b * CINn * Nn + (size_t)c * Nn + idx];
    }
}

extern "C" void kernel_launch(void* const* d_in, const int* in_sizes, int n_in,
                              void* d_out, int out_size)
{
    const float* xyz  = (const float*)d_in[0];  // [B,3,N]
    const float* feat = (const float*)d_in[1];  // [B,Cin,N]
    float* out = (float*)d_out;

    fps_kernel<<<Bn * CLUSTER, THREADS>>>(xyz);

    const int TOT = Bn * 3 * Mn + Bn * CINn * Mn;
    gather_kernel<<<(TOT + 255) / 256, 256>>>(xyz, feat, out);
}